// round 10
// baseline (speedup 1.0000x reference)
#include <cuda_runtime.h>

// ---------------------------------------------------------------------------
// ImprovedAILayerNorm: int8-quantized layernorm with LUT integer sqrt.
// R10 = R9 (PDL chain, serpentine L2, ldcs/stcs) with 4 rows/block in the
// two reduction passes: 8 independent LDG.128 in flight per thread, one
// __syncthreads per 4 rows, 4 leader threads finalize rows concurrently.
// ---------------------------------------------------------------------------

#define T2 512
#define NWARP (T2 / 32)
#define MAX_ROWS 32768

__device__ int   g_absmax_bits;
__device__ int   g_ymax_bits;
__device__ int   g_const_flag;
__device__ float g_g0, g_b0;
__device__ float g_mu[MAX_ROWS];
__device__ float g_inv_std[MAX_ROWS];
__device__ float g_rowmin[MAX_ROWS];
__device__ float g_rowmax[MAX_ROWS];

__device__ __forceinline__ void pdl_launch_dependents() {
    asm volatile("griddepcontrol.launch_dependents;" ::: "memory");
}
__device__ __forceinline__ void pdl_wait() {
    asm volatile("griddepcontrol.wait;" ::: "memory");
}

// ---------------------------------------------------------------------------
__global__ void k_init_check(const float* __restrict__ gamma,
                             const float* __restrict__ beta, int N) {
    pdl_launch_dependents();
    if (threadIdx.x == 0) {
        g_absmax_bits = 0;
        g_ymax_bits   = 0;
        g_const_flag  = 1;
        g_g0 = gamma[0];
        g_b0 = beta[0];
    }
    __syncthreads();
    float g0 = g_g0, b0 = g_b0;
    bool bad = false;
    for (int i = threadIdx.x; i < N; i += blockDim.x)
        bad |= (gamma[i] != g0) || (beta[i] != b0);
    if (__syncthreads_or(bad) && threadIdx.x == 0) g_const_flag = 0;
}

// ordered-uint mapping for float min/max redux
__device__ __forceinline__ unsigned f2ord(float f) {
    unsigned u = __float_as_uint(f);
    return (u & 0x80000000u) ? ~u : (u | 0x80000000u);
}
__device__ __forceinline__ float ord2f(unsigned u) {
    return __uint_as_float((u & 0x80000000u) ? (u & 0x7fffffffu) : ~u);
}

__device__ __forceinline__ float v4min(float4 v) {
    return fminf(fminf(v.x, v.y), fminf(v.z, v.w));
}
__device__ __forceinline__ float v4max(float4 v) {
    return fmaxf(fmaxf(v.x, v.y), fmaxf(v.z, v.w));
}

// ---------------------------------------------------------------------------
// Pass 1: 4 rows/block, row min/max + global absmax. ASCENDING rows.
__global__ void __launch_bounds__(T2)
k_minmax(const float* __restrict__ x, int N) {
    pdl_launch_dependents();
    const int r0 = blockIdx.x * 4;
    const float4* x0 = reinterpret_cast<const float4*>(x + (size_t)r0 * N);
    const float4* x1 = reinterpret_cast<const float4*>(x + (size_t)(r0 + 1) * N);
    const float4* x2 = reinterpret_cast<const float4*>(x + (size_t)(r0 + 2) * N);
    const float4* x3 = reinterpret_cast<const float4*>(x + (size_t)(r0 + 3) * N);

    // 8 independent loads up front
    float4 a0 = x0[threadIdx.x],      a1 = x0[T2 + threadIdx.x];
    float4 b0 = x1[threadIdx.x],      b1 = x1[T2 + threadIdx.x];
    float4 c0 = x2[threadIdx.x],      c1 = x2[T2 + threadIdx.x];
    float4 d0 = x3[threadIdx.x],      d1 = x3[T2 + threadIdx.x];

    unsigned wmn[4], wmx[4];
    {
        float mn, mx;
        mn = fminf(v4min(a0), v4min(a1)); mx = fmaxf(v4max(a0), v4max(a1));
        wmn[0] = __reduce_min_sync(0xffffffffu, f2ord(mn));
        wmx[0] = __reduce_max_sync(0xffffffffu, f2ord(mx));
        mn = fminf(v4min(b0), v4min(b1)); mx = fmaxf(v4max(b0), v4max(b1));
        wmn[1] = __reduce_min_sync(0xffffffffu, f2ord(mn));
        wmx[1] = __reduce_max_sync(0xffffffffu, f2ord(mx));
        mn = fminf(v4min(c0), v4min(c1)); mx = fmaxf(v4max(c0), v4max(c1));
        wmn[2] = __reduce_min_sync(0xffffffffu, f2ord(mn));
        wmx[2] = __reduce_max_sync(0xffffffffu, f2ord(mx));
        mn = fminf(v4min(d0), v4min(d1)); mx = fmaxf(v4max(d0), v4max(d1));
        wmn[3] = __reduce_min_sync(0xffffffffu, f2ord(mn));
        wmx[3] = __reduce_max_sync(0xffffffffu, f2ord(mx));
    }

    __shared__ unsigned smn[4][NWARP], smx[4][NWARP];
    const int w = threadIdx.x >> 5;
    if ((threadIdx.x & 31) == 0) {
        #pragma unroll
        for (int r = 0; r < 4; r++) { smn[r][w] = wmn[r]; smx[r][w] = wmx[r]; }
    }
    __syncthreads();
    // 4 leaders finalize 4 rows concurrently
    if (threadIdx.x < 128 && (threadIdx.x & 31) == 0) {
        const int r = threadIdx.x >> 5;              // 0..3
        unsigned umn = 0xffffffffu, umx = 0u;
        #pragma unroll
        for (int i = 0; i < NWARP; i++) {
            umn = min(umn, smn[r][i]);
            umx = max(umx, smx[r][i]);
        }
        float fmn = ord2f(umn), fmx = ord2f(umx);
        g_rowmin[r0 + r] = fmn;
        g_rowmax[r0 + r] = fmx;
        float am = fmaxf(fabsf(fmn), fabsf(fmx));
        pdl_wait();                                  // init's zeroing visible
        atomicMax(&g_absmax_bits, (int)__float_as_uint(am));
    }
}

// ---------------------------------------------------------------------------
// Exact replica of reference sqrt_rounded_vec (LUT-based rounded int sqrt)
__device__ __forceinline__ float sqrt_rounded(int d) {
    int msb = 31 - __clz(d);
    int k   = msb >> 1;
    int dn  = d << ((7 - k) * 2);
    int addr = (dn >> 8) & 255;
    int v    = addr * 256 + 128;
    int mant = (int)sqrtf((float)v);
    if (mant * mant > v) mant--;
    if ((mant + 1) * (mant + 1) <= v) mant++;
    int qf = mant >> (7 - k);
    int boundary = qf * qf + qf;
    return (float)((d > boundary) ? qf + 1 : qf);
}

__device__ __forceinline__ void row_finalize(int row, int t, int t2,
                                             float s, int N, bool cst) {
    float Ex  = (float)t  * s;
    float Ex2 = (float)t2 * (s * s);
    float mu  = Ex / (float)N;
    float var = fmaxf(Ex2 / (float)N - mu * mu, 0.0f);
    float vi  = fminf(fmaxf(rintf(var), 1.0f), 65535.0f);
    float inv = 1.0f / fmaxf(sqrt_rounded((int)vi), 1e-5f);
    g_mu[row] = mu;
    g_inv_std[row] = inv;
    if (cst) {
        float g0 = g_g0, b0 = g_b0;
        float y1 = fabsf((g_rowmax[row] - mu) * inv * g0 + b0);
        float y2 = fabsf((g_rowmin[row] - mu) * inv * g0 + b0);
        atomicMax(&g_ymax_bits, (int)__float_as_uint(fmaxf(y1, y2)));
    }
}

__device__ __forceinline__ void acc8(float4 p, float4 q, float inv_s,
                                     int& su, int& su2) {
    #pragma unroll
    for (int c = 0; c < 4; c++) {
        int q0 = __float2int_rn((&p.x)[c] * inv_s);
        int q1 = __float2int_rn((&q.x)[c] * inv_s);
        su  += q0 + q1;
        su2 += q0 * q0 + q1 * q1;
    }
}

// ---------------------------------------------------------------------------
// Pass 2: 4 rows/block int moments, DESCENDING. No clamps
// (|x|/s <= 127 by construction of s). x preloaded before pdl_wait.
__global__ void __launch_bounds__(T2)
k_rowstats(const float* __restrict__ x,
           const float* __restrict__ gamma,
           const float* __restrict__ beta,
           int N, int rows) {
    pdl_launch_dependents();
    const int r0 = rows - 4 - blockIdx.x * 4;        // quad, descending
    const float4* x0 = reinterpret_cast<const float4*>(x + (size_t)r0 * N);
    const float4* x1 = reinterpret_cast<const float4*>(x + (size_t)(r0 + 1) * N);
    const float4* x2 = reinterpret_cast<const float4*>(x + (size_t)(r0 + 2) * N);
    const float4* x3 = reinterpret_cast<const float4*>(x + (size_t)(r0 + 3) * N);

    // preload 8 independent float4 (x doesn't depend on producer)
    float4 a0 = x0[threadIdx.x],      a1 = x0[T2 + threadIdx.x];
    float4 b0 = x1[threadIdx.x],      b1 = x1[T2 + threadIdx.x];
    float4 c0 = x2[threadIdx.x],      c1 = x2[T2 + threadIdx.x];
    float4 d0 = x3[threadIdx.x],      d1 = x3[T2 + threadIdx.x];

    pdl_wait();                                      // absmax/flag final
    const bool cst = (g_const_flag != 0);
    const float s     = fmaxf(__int_as_float(g_absmax_bits) / 127.0f, 1e-8f);
    const float inv_s = 1.0f / s;

    int su[4] = {0, 0, 0, 0}, su2[4] = {0, 0, 0, 0};
    acc8(a0, a1, inv_s, su[0], su2[0]);
    acc8(b0, b1, inv_s, su[1], su2[1]);
    acc8(c0, c1, inv_s, su[2], su2[2]);
    acc8(d0, d1, inv_s, su[3], su2[3]);

    __shared__ int sw[8][NWARP];
    const int w = threadIdx.x >> 5;
    #pragma unroll
    for (int r = 0; r < 4; r++) {
        int t  = __reduce_add_sync(0xffffffffu, su[r]);
        int t2 = __reduce_add_sync(0xffffffffu, su2[r]);
        if ((threadIdx.x & 31) == 0) { sw[2 * r][w] = t; sw[2 * r + 1][w] = t2; }
    }
    __syncthreads();
    if (threadIdx.x < 128 && (threadIdx.x & 31) == 0) {
        const int r = threadIdx.x >> 5;              // 0..3
        int t = 0, t2 = 0;
        #pragma unroll
        for (int i = 0; i < NWARP; i++) {
            t  += sw[2 * r][i];
            t2 += sw[2 * r + 1][i];
        }
        row_finalize(r0 + r, t, t2, s, N, cst);
    }
    if (cst) return;

    // ---- general gamma/beta path: sweep 4 rows for max|y| ----
    __syncthreads();
    const float4* g4 = reinterpret_cast<const float4*>(gamma);
    const float4* b4 = reinterpret_cast<const float4*>(beta);
    float ymax = 0.0f;
    #pragma unroll
    for (int r = 0; r < 4; r++) {
        const float mu = g_mu[r0 + r];
        const float is = g_inv_std[r0 + r];
        const float4* xr = reinterpret_cast<const float4*>(x + (size_t)(r0 + r) * N);
        #pragma unroll
        for (int j = 0; j < 2; j++) {
            float4 v = xr[j * T2 + threadIdx.x];
            float4 g = g4[j * T2 + threadIdx.x];
            float4 b = b4[j * T2 + threadIdx.x];
            #pragma unroll
            for (int c = 0; c < 4; c++) {
                float y = ((&v.x)[c] - mu) * is * (&g.x)[c] + (&b.x)[c];
                ymax = fmaxf(ymax, fabsf(y));
            }
        }
    }
    unsigned yb = __reduce_max_sync(0xffffffffu, __float_as_uint(ymax));
    __shared__ unsigned sy[NWARP];
    if ((threadIdx.x & 31) == 0) sy[w] = yb;
    __syncthreads();
    if (threadIdx.x == 0) {
        unsigned v = 0;
        #pragma unroll
        for (int i = 0; i < NWARP; i++) v = max(v, sy[i]);
        atomicMax(&g_ymax_bits, (int)v);
    }
}

// ---------------------------------------------------------------------------
// Pass 3: 1 row/block, ASCENDING (rides pass-2 residency). ldcs/stcs.
// x preloaded before pdl_wait. (Unchanged from R9 — already at roofline.)
__global__ void __launch_bounds__(T2)
k_quant(const float* __restrict__ x,
        const float* __restrict__ gamma,
        const float* __restrict__ beta,
        float* __restrict__ out,
        int N) {
    const int row = blockIdx.x;
    const float4* xr = reinterpret_cast<const float4*>(x + (size_t)row * N);
    float4* orow = reinterpret_cast<float4*>(out + (size_t)row * N);

    float4 v0 = __ldcs(&xr[threadIdx.x]);
    float4 v1 = __ldcs(&xr[T2 + threadIdx.x]);

    pdl_wait();                                      // mu/inv_std/ymax final
    const float mu = g_mu[row];
    const float is = g_inv_std[row];
    const float so     = fmaxf(__int_as_float(g_ymax_bits) / 127.0f, 1e-8f);
    const float inv_so = 1.0f / so;

    if (g_const_flag) {
        const float g0 = g_g0, b0 = g_b0;
        const float A2 = is * g0 * inv_so;
        const float B2 = (b0 - mu * is * g0) * inv_so;
        float4 o0, o1;
        #pragma unroll
        for (int c = 0; c < 4; c++) {
            int q0 = __float2int_rn(fmaf((&v0.x)[c], A2, B2));
            int q1 = __float2int_rn(fmaf((&v1.x)[c], A2, B2));
            q0 = max(-127, min(127, q0));            // safety vs reassoc ulp
            q1 = max(-127, min(127, q1));
            (&o0.x)[c] = (float)q0 * so;
            (&o1.x)[c] = (float)q1 * so;
        }
        __stcs(&orow[threadIdx.x], o0);
        __stcs(&orow[T2 + threadIdx.x], o1);
        return;
    }

    const float4* g4 = reinterpret_cast<const float4*>(gamma);
    const float4* b4 = reinterpret_cast<const float4*>(beta);
    float4 ga = g4[threadIdx.x], gb = g4[T2 + threadIdx.x];
    float4 ba = b4[threadIdx.x], bb = b4[T2 + threadIdx.x];
    float4 o0, o1;
    #pragma unroll
    for (int c = 0; c < 4; c++) {
        float y0 = ((&v0.x)[c] - mu) * is * (&ga.x)[c] + (&ba.x)[c];
        float y1 = ((&v1.x)[c] - mu) * is * (&gb.x)[c] + (&bb.x)[c];
        (&o0.x)[c] = (float)__float2int_rn(y0 * inv_so) * so;
        (&o1.x)[c] = (float)__float2int_rn(y1 * inv_so) * so;
    }
    __stcs(&orow[threadIdx.x], o0);
    __stcs(&orow[T2 + threadIdx.x], o1);
}

// ---------------------------------------------------------------------------
static void launch_pdl(void* func, dim3 grid, dim3 block, void** args) {
    cudaLaunchConfig_t cfg = {};
    cfg.gridDim = grid;
    cfg.blockDim = block;
    cfg.stream = 0;
    cudaLaunchAttribute attr[1];
    attr[0].id = cudaLaunchAttributeProgrammaticStreamSerialization;
    attr[0].val.programmaticStreamSerializationAllowed = 1;
    cfg.attrs = attr;
    cfg.numAttrs = 1;
    cudaLaunchKernelExC(&cfg, func, args);
}

extern "C" void kernel_launch(void* const* d_in, const int* in_sizes, int n_in,
                              void* d_out, int out_size) {
    const float* x     = (const float*)d_in[0];
    const float* gamma = (const float*)d_in[1];
    const float* beta  = (const float*)d_in[2];
    float* out = (float*)d_out;

    int N    = in_sizes[1];              // 4096
    const int n = in_sizes[0];           // 4*2048*4096
    int rows = n / N;                    // 8192

    {   // init+check (plain launch)
        void* args[] = {(void*)&gamma, (void*)&beta, (void*)&N};
        cudaLaunchConfig_t cfg = {};
        cfg.gridDim = dim3(1); cfg.blockDim = dim3(T2); cfg.stream = 0;
        cudaLaunchKernelExC(&cfg, (void*)k_init_check, args);
    }
    {   // pass 1 (PDL after init)
        void* args[] = {(void*)&x, (void*)&N};
        launch_pdl((void*)k_minmax, dim3(rows / 4), dim3(T2), args);
    }
    {   // pass 2 (PDL after pass 1)
        void* args[] = {(void*)&x, (void*)&gamma, (void*)&beta,
                        (void*)&N, (void*)&rows};
        launch_pdl((void*)k_rowstats, dim3(rows / 4), dim3(T2), args);
    }
    {   // pass 3 (PDL after pass 2)
        void* args[] = {(void*)&x, (void*)&gamma, (void*)&beta,
                        (void*)&out, (void*)&N};
        launch_pdl((void*)k_quant, dim3(rows), dim3(T2), args);
    }
}

// round 12
// speedup vs baseline: 1.0058x; 1.0058x over previous
#include <cuda_runtime.h>

// ---------------------------------------------------------------------------
// ImprovedAILayerNorm: int8-quantized layernorm with LUT integer sqrt.
// R12 = R9 (PDL chain, serpentine, ldcs/stcs) + L2 evict_last on x in the
// two reduction passes, via 256-bit loads (sm_103a requires .v8.b32 for the
// evict_last modifier). 512 thr x 32B = one 16KB row per load sweep.
// ---------------------------------------------------------------------------

#define T2 512
#define NWARP (T2 / 32)
#define MAX_ROWS 32768

__device__ int   g_absmax_bits;
__device__ int   g_ymax_bits;
__device__ int   g_const_flag;
__device__ float g_g0, g_b0;
__device__ float g_mu[MAX_ROWS];
__device__ float g_inv_std[MAX_ROWS];
__device__ float g_rowmin[MAX_ROWS];
__device__ float g_rowmax[MAX_ROWS];

__device__ __forceinline__ void pdl_launch_dependents() {
    asm volatile("griddepcontrol.launch_dependents;" ::: "memory");
}
__device__ __forceinline__ void pdl_wait() {
    asm volatile("griddepcontrol.wait;" ::: "memory");
}

struct F8 { float v[8]; };

// 256-bit load with L2 evict_last (keep x resident across passes)
__device__ __forceinline__ F8 ldg_keep8(const float* p) {
    unsigned u0, u1, u2, u3, u4, u5, u6, u7;
    asm volatile(
        "ld.global.L2::evict_last.v8.b32 {%0,%1,%2,%3,%4,%5,%6,%7}, [%8];"
        : "=r"(u0), "=r"(u1), "=r"(u2), "=r"(u3),
          "=r"(u4), "=r"(u5), "=r"(u6), "=r"(u7)
        : "l"(p));
    F8 r;
    r.v[0] = __uint_as_float(u0); r.v[1] = __uint_as_float(u1);
    r.v[2] = __uint_as_float(u2); r.v[3] = __uint_as_float(u3);
    r.v[4] = __uint_as_float(u4); r.v[5] = __uint_as_float(u5);
    r.v[6] = __uint_as_float(u6); r.v[7] = __uint_as_float(u7);
    return r;
}

// ---------------------------------------------------------------------------
__global__ void k_init_check(const float* __restrict__ gamma,
                             const float* __restrict__ beta, int N) {
    pdl_launch_dependents();
    if (threadIdx.x == 0) {
        g_absmax_bits = 0;
        g_ymax_bits   = 0;
        g_const_flag  = 1;
        g_g0 = gamma[0];
        g_b0 = beta[0];
    }
    __syncthreads();
    float g0 = g_g0, b0 = g_b0;
    bool bad = false;
    for (int i = threadIdx.x; i < N; i += blockDim.x)
        bad |= (gamma[i] != g0) || (beta[i] != b0);
    if (__syncthreads_or(bad) && threadIdx.x == 0) g_const_flag = 0;
}

// ordered-uint mapping for float min/max redux
__device__ __forceinline__ unsigned f2ord(float f) {
    unsigned u = __float_as_uint(f);
    return (u & 0x80000000u) ? ~u : (u | 0x80000000u);
}
__device__ __forceinline__ float ord2f(unsigned u) {
    return __uint_as_float((u & 0x80000000u) ? (u & 0x7fffffffu) : ~u);
}

// ---------------------------------------------------------------------------
// Pass 1: 2 rows/block, row min/max + global absmax. ASCENDING rows.
// One 256-bit evict_last load per row per thread.
__global__ void __launch_bounds__(T2)
k_minmax(const float* __restrict__ x, int N) {
    pdl_launch_dependents();
    const int r0 = blockIdx.x * 2;
    const float* xa = x + (size_t)r0 * N + threadIdx.x * 8;
    const float* xb = x + (size_t)(r0 + 1) * N + threadIdx.x * 8;

    F8 a = ldg_keep8(xa);
    F8 b = ldg_keep8(xb);

    float mnA = a.v[0], mxA = a.v[0];
    float mnB = b.v[0], mxB = b.v[0];
    #pragma unroll
    for (int c = 1; c < 8; c++) {
        mnA = fminf(mnA, a.v[c]); mxA = fmaxf(mxA, a.v[c]);
        mnB = fminf(mnB, b.v[c]); mxB = fmaxf(mxB, b.v[c]);
    }

    unsigned wmnA = __reduce_min_sync(0xffffffffu, f2ord(mnA));
    unsigned wmxA = __reduce_max_sync(0xffffffffu, f2ord(mxA));
    unsigned wmnB = __reduce_min_sync(0xffffffffu, f2ord(mnB));
    unsigned wmxB = __reduce_max_sync(0xffffffffu, f2ord(mxB));

    __shared__ unsigned smn[2][NWARP], smx[2][NWARP];
    const int w = threadIdx.x >> 5;
    if ((threadIdx.x & 31) == 0) {
        smn[0][w] = wmnA; smx[0][w] = wmxA;
        smn[1][w] = wmnB; smx[1][w] = wmxB;
    }
    __syncthreads();
    if (threadIdx.x == 0 || threadIdx.x == 32) {
        const int r = threadIdx.x >> 5;         // 0 or 1
        unsigned umn = 0xffffffffu, umx = 0u;
        #pragma unroll
        for (int i = 0; i < NWARP; i++) {
            umn = min(umn, smn[r][i]);
            umx = max(umx, smx[r][i]);
        }
        float fmn = ord2f(umn), fmx = ord2f(umx);
        g_rowmin[r0 + r] = fmn;
        g_rowmax[r0 + r] = fmx;
        float am = fmaxf(fabsf(fmn), fabsf(fmx));
        pdl_wait();                              // init's zeroing visible
        atomicMax(&g_absmax_bits, (int)__float_as_uint(am));
    }
}

// ---------------------------------------------------------------------------
// Exact replica of reference sqrt_rounded_vec (LUT-based rounded int sqrt)
__device__ __forceinline__ float sqrt_rounded(int d) {
    int msb = 31 - __clz(d);
    int k   = msb >> 1;
    int dn  = d << ((7 - k) * 2);
    int addr = (dn >> 8) & 255;
    int v    = addr * 256 + 128;
    int mant = (int)sqrtf((float)v);
    if (mant * mant > v) mant--;
    if ((mant + 1) * (mant + 1) <= v) mant++;
    int qf = mant >> (7 - k);
    int boundary = qf * qf + qf;
    return (float)((d > boundary) ? qf + 1 : qf);
}

__device__ __forceinline__ void row_finalize(int row, int t, int t2,
                                             float s, int N, bool cst) {
    float Ex  = (float)t  * s;
    float Ex2 = (float)t2 * (s * s);
    float mu  = Ex / (float)N;
    float var = fmaxf(Ex2 / (float)N - mu * mu, 0.0f);
    float vi  = fminf(fmaxf(rintf(var), 1.0f), 65535.0f);
    float inv = 1.0f / fmaxf(sqrt_rounded((int)vi), 1e-5f);
    g_mu[row] = mu;
    g_inv_std[row] = inv;
    if (cst) {
        float g0 = g_g0, b0 = g_b0;
        float y1 = fabsf((g_rowmax[row] - mu) * inv * g0 + b0);
        float y2 = fabsf((g_rowmin[row] - mu) * inv * g0 + b0);
        atomicMax(&g_ymax_bits, (int)__float_as_uint(fmaxf(y1, y2)));
    }
}

// ---------------------------------------------------------------------------
// Pass 2: 2 rows/block int moments, DESCENDING. No clamps
// (|x|/s <= 127 by construction of s). x preloaded (evict_last) pre-wait.
__global__ void __launch_bounds__(T2)
k_rowstats(const float* __restrict__ x,
           const float* __restrict__ gamma,
           const float* __restrict__ beta,
           int N, int rows) {
    pdl_launch_dependents();
    const int r0 = rows - 2 - blockIdx.x * 2;          // pair, descending
    const float* xa = x + (size_t)r0 * N + threadIdx.x * 8;
    const float* xb = x + (size_t)(r0 + 1) * N + threadIdx.x * 8;

    // preload x (independent of producer results), keep resident for pass 3
    F8 a = ldg_keep8(xa);
    F8 b = ldg_keep8(xb);

    pdl_wait();                                        // absmax/flag final
    const bool cst = (g_const_flag != 0);
    const float s     = fmaxf(__int_as_float(g_absmax_bits) / 127.0f, 1e-8f);
    const float inv_s = 1.0f / s;

    int sA = 0, s2A = 0, sB = 0, s2B = 0;
    #pragma unroll
    for (int c = 0; c < 8; c++) {
        int qa = __float2int_rn(a.v[c] * inv_s);       // RN half-even
        int qb = __float2int_rn(b.v[c] * inv_s);
        sA += qa;  s2A += qa * qa;
        sB += qb;  s2B += qb * qb;
    }
    sA  = __reduce_add_sync(0xffffffffu, sA);
    s2A = __reduce_add_sync(0xffffffffu, s2A);
    sB  = __reduce_add_sync(0xffffffffu, sB);
    s2B = __reduce_add_sync(0xffffffffu, s2B);

    __shared__ int sw[4][NWARP];
    const int w = threadIdx.x >> 5;
    if ((threadIdx.x & 31) == 0) {
        sw[0][w] = sA;  sw[1][w] = s2A;
        sw[2][w] = sB;  sw[3][w] = s2B;
    }
    __syncthreads();
    if (threadIdx.x == 0 || threadIdx.x == 32) {
        const int r = threadIdx.x >> 5;                // 0 or 1
        int t = 0, t2 = 0;
        #pragma unroll
        for (int i = 0; i < NWARP; i++) {
            t  += sw[2 * r][i];
            t2 += sw[2 * r + 1][i];
        }
        row_finalize(r0 + r, t, t2, s, N, cst);
    }
    if (cst) return;

    // ---- general gamma/beta path: sweep both rows for max|y| ----
    __syncthreads();
    const float* gp = gamma + threadIdx.x * 8;
    const float* bp = beta  + threadIdx.x * 8;
    float ymax = 0.0f;
    {
        const float muA = g_mu[r0],     isA = g_inv_std[r0];
        const float muB = g_mu[r0 + 1], isB = g_inv_std[r0 + 1];
        #pragma unroll
        for (int c = 0; c < 8; c++) {
            float gv = gp[c], bv = bp[c];
            float yA = (a.v[c] - muA) * isA * gv + bv;
            float yB = (b.v[c] - muB) * isB * gv + bv;
            ymax = fmaxf(ymax, fmaxf(fabsf(yA), fabsf(yB)));
        }
    }
    unsigned yb = __reduce_max_sync(0xffffffffu, __float_as_uint(ymax));
    __shared__ unsigned sy[NWARP];
    if ((threadIdx.x & 31) == 0) sy[w] = yb;
    __syncthreads();
    if (threadIdx.x == 0) {
        unsigned v = 0;
        #pragma unroll
        for (int i = 0; i < NWARP; i++) v = max(v, sy[i]);
        atomicMax(&g_ymax_bits, (int)v);
    }
}

// ---------------------------------------------------------------------------
// Pass 3: 1 row/block, ASCENDING (rides pass-2 residency). x evict-first
// (last use), out streamed with __stcs. x preloaded before pdl_wait.
__global__ void __launch_bounds__(T2)
k_quant(const float* __restrict__ x,
        const float* __restrict__ gamma,
        const float* __restrict__ beta,
        float* __restrict__ out,
        int N) {
    const int row = blockIdx.x;
    const float4* xr = reinterpret_cast<const float4*>(x + (size_t)row * N);
    float4* orow = reinterpret_cast<float4*>(out + (size_t)row * N);

    float4 v0 = __ldcs(&xr[threadIdx.x]);
    float4 v1 = __ldcs(&xr[T2 + threadIdx.x]);

    pdl_wait();                                        // mu/inv_std/ymax final
    const float mu = g_mu[row];
    const float is = g_inv_std[row];
    const float so     = fmaxf(__int_as_float(g_ymax_bits) / 127.0f, 1e-8f);
    const float inv_so = 1.0f / so;

    if (g_const_flag) {
        const float g0 = g_g0, b0 = g_b0;
        const float A2 = is * g0 * inv_so;
        const float B2 = (b0 - mu * is * g0) * inv_so;
        float4 o0, o1;
        #pragma unroll
        for (int c = 0; c < 4; c++) {
            int q0 = __float2int_rn(fmaf((&v0.x)[c], A2, B2));
            int q1 = __float2int_rn(fmaf((&v1.x)[c], A2, B2));
            q0 = max(-127, min(127, q0));              // safety vs reassoc ulp
            q1 = max(-127, min(127, q1));
            (&o0.x)[c] = (float)q0 * so;
            (&o1.x)[c] = (float)q1 * so;
        }
        __stcs(&orow[threadIdx.x], o0);
        __stcs(&orow[T2 + threadIdx.x], o1);
        return;
    }

    const float4* g4 = reinterpret_cast<const float4*>(gamma);
    const float4* b4 = reinterpret_cast<const float4*>(beta);
    float4 ga = g4[threadIdx.x], gb = g4[T2 + threadIdx.x];
    float4 ba = b4[threadIdx.x], bb = b4[T2 + threadIdx.x];
    float4 o0, o1;
    #pragma unroll
    for (int c = 0; c < 4; c++) {
        float y0 = ((&v0.x)[c] - mu) * is * (&ga.x)[c] + (&ba.x)[c];
        float y1 = ((&v1.x)[c] - mu) * is * (&gb.x)[c] + (&bb.x)[c];
        (&o0.x)[c] = (float)__float2int_rn(y0 * inv_so) * so;
        (&o1.x)[c] = (float)__float2int_rn(y1 * inv_so) * so;
    }
    __stcs(&orow[threadIdx.x], o0);
    __stcs(&orow[T2 + threadIdx.x], o1);
}

// ---------------------------------------------------------------------------
static void launch_pdl(void* func, dim3 grid, dim3 block, void** args) {
    cudaLaunchConfig_t cfg = {};
    cfg.gridDim = grid;
    cfg.blockDim = block;
    cfg.stream = 0;
    cudaLaunchAttribute attr[1];
    attr[0].id = cudaLaunchAttributeProgrammaticStreamSerialization;
    attr[0].val.programmaticStreamSerializationAllowed = 1;
    cfg.attrs = attr;
    cfg.numAttrs = 1;
    cudaLaunchKernelExC(&cfg, func, args);
}

extern "C" void kernel_launch(void* const* d_in, const int* in_sizes, int n_in,
                              void* d_out, int out_size) {
    const float* x     = (const float*)d_in[0];
    const float* gamma = (const float*)d_in[1];
    const float* beta  = (const float*)d_in[2];
    float* out = (float*)d_out;

    int N    = in_sizes[1];              // 4096
    const int n = in_sizes[0];           // 4*2048*4096
    int rows = n / N;                    // 8192

    {   // init+check (plain launch)
        void* args[] = {(void*)&gamma, (void*)&beta, (void*)&N};
        cudaLaunchConfig_t cfg = {};
        cfg.gridDim = dim3(1); cfg.blockDim = dim3(T2); cfg.stream = 0;
        cudaLaunchKernelExC(&cfg, (void*)k_init_check, args);
    }
    {   // pass 1 (PDL after init)
        void* args[] = {(void*)&x, (void*)&N};
        launch_pdl((void*)k_minmax, dim3(rows / 2), dim3(T2), args);
    }
    {   // pass 2 (PDL after pass 1)
        void* args[] = {(void*)&x, (void*)&gamma, (void*)&beta,
                        (void*)&N, (void*)&rows};
        launch_pdl((void*)k_rowstats, dim3(rows / 2), dim3(T2), args);
    }
    {   // pass 3 (PDL after pass 2)
        void* args[] = {(void*)&x, (void*)&gamma, (void*)&beta,
                        (void*)&out, (void*)&N};
        launch_pdl((void*)k_quant, dim3(rows), dim3(T2), args);
    }
}